// round 6
// baseline (speedup 1.0000x reference)
#include <cuda_runtime.h>
#include <cuda_bf16.h>
#include <cub/cub.cuh>
#include <math.h>

#define NNODES 10000
#define BATCH  2000
#define NPAIRS (BATCH*(BATCH-1)/2)   /* 1999000 */
#define EMAX   5000000
#define SEL_THREADS 1024
#define ROWCAP 768                   /* per-row capacity: mean 500, +12 sigma */

// ---------------- static device scratch (no allocations allowed) -----------
__device__ unsigned int g_kin [EMAX];
__device__ unsigned int g_kout[EMAX];
__device__ unsigned int g_vin [EMAX];
__device__ unsigned int g_vout[EMAX];
__device__ unsigned int g_rcnt[NNODES];
__device__ unsigned int g_roff[NNODES + 1];
__device__ unsigned int g_scores[NNODES];
__device__ unsigned int g_nodes[BATCH];
__device__ int          g_flags[NNODES];
__device__ unsigned char g_temp[96u * 1024u * 1024u];

__device__ __forceinline__ unsigned int rotl32(unsigned int x, unsigned int d) {
    return (x << d) | (x >> (32u - d));
}

// ---------------- node chain: scores / select / pairs ----------------------
__global__ void k_scores() {
    int w = blockIdx.x * blockDim.x + threadIdx.x;
    if (w >= NNODES) return;
    const unsigned int k0 = 0u, k1 = 19u;
    const unsigned int ks[3] = { k0, k1, k0 ^ k1 ^ 0x1BD11BDAu };
    const unsigned int rotA[4] = {13u, 15u, 26u, 6u};
    const unsigned int rotB[4] = {17u, 29u, 16u, 24u};
    unsigned int x0 = 0u, x1 = (unsigned int)w;
    x0 += ks[0]; x1 += ks[1];
    #pragma unroll
    for (int i = 0; i < 5; i++) {
        #pragma unroll
        for (int r = 0; r < 4; r++) {
            unsigned int rot = (i & 1) ? rotB[r] : rotA[r];
            x0 += x1; x1 = rotl32(x1, rot); x1 ^= x0;
        }
        x0 += ks[(i + 1) % 3];
        x1 += ks[(i + 2) % 3] + (unsigned int)(i + 1);
    }
    unsigned int bits = x0 ^ x1;
    float f = __uint_as_float((bits >> 9) | 0x3F800000u) - 1.0f;
    float u = fmaxf(f, 1.17549435e-38f);
    float g = -logf(-logf(u));
    float s = (w > 0) ? (logf((float)w) + g) : -INFINITY;
    unsigned int b = __float_as_uint(s);
    unsigned int m = (b & 0x80000000u) ? ~b : (b | 0x80000000u);
    g_scores[w] = m;
}

__global__ void __launch_bounds__(SEL_THREADS) k_select(float* __restrict__ out) {
    __shared__ unsigned int s[NNODES];
    __shared__ unsigned int hist[256];
    __shared__ unsigned int sh_b, sh_rem, sh_run_eq, sh_run_sel;
    typedef cub::BlockScan<unsigned int, SEL_THREADS> Scan;
    __shared__ typename Scan::TempStorage scan_tmp;

    int tid = threadIdx.x;
    for (int e = tid; e < NNODES; e += SEL_THREADS) s[e] = g_scores[e];
    if (tid == 0) { sh_rem = BATCH; sh_run_eq = 0; sh_run_sel = 0; }
    __syncthreads();

    unsigned int prefix = 0;
    #pragma unroll
    for (int shift = 24; shift >= 0; shift -= 8) {
        if (tid < 256) hist[tid] = 0;
        __syncthreads();
        unsigned int mask_hi = (shift == 24) ? 0u : (0xFFFFFFFFu << (shift + 8));
        for (int e = tid; e < NNODES; e += SEL_THREADS) {
            unsigned int v = s[e];
            if (((v ^ prefix) & mask_hi) == 0u)
                atomicAdd(&hist[(v >> shift) & 255u], 1u);
        }
        __syncthreads();
        if (tid == 0) {
            unsigned int rem = sh_rem, acc = 0; int b = 0;
            for (int k = 255; k >= 0; k--) {
                unsigned int c = hist[k];
                if (acc + c >= rem) { b = k; break; }
                acc += c;
            }
            sh_b = (unsigned int)b; sh_rem = rem - acc;
        }
        __syncthreads();
        prefix |= sh_b << shift;
        __syncthreads();
    }
    unsigned int thr = prefix, rem = sh_rem;

    for (int base = 0; base < NNODES; base += SEL_THREADS) {
        int e = base + tid;
        unsigned int v = (e < NNODES) ? s[e] : 0u;
        unsigned int is_eq = (e < NNODES && v == thr) ? 1u : 0u;
        unsigned int is_gt = (e < NNODES && v >  thr) ? 1u : 0u;
        unsigned int eq_rank, eq_tot;
        Scan(scan_tmp).ExclusiveSum(is_eq, eq_rank, eq_tot);
        __syncthreads();
        unsigned int sel = is_gt | ((is_eq && (sh_run_eq + eq_rank) < rem) ? 1u : 0u);
        unsigned int pos, sel_tot;
        Scan(scan_tmp).ExclusiveSum(sel, pos, sel_tot);
        __syncthreads();
        unsigned int gpos = sh_run_sel + pos;
        if (e < NNODES) {
            g_flags[e] = (int)sel;
            if (sel) { g_nodes[gpos] = (unsigned int)e; out[gpos] = (float)e; }
        }
        __syncthreads();
        if (tid == 0) { sh_run_eq += eq_tot; sh_run_sel += sel_tot; }
        __syncthreads();
    }
}

__global__ void k_pairs(float* __restrict__ out) {
    int p = blockIdx.x * blockDim.x + threadIdx.x;
    if (p >= NPAIRS) return;
    const float A = 2.0f * BATCH - 1.0f;
    float disc = A * A - 8.0f * (float)p;
    int i = (int)((A - sqrtf(fmaxf(disc, 0.0f))) * 0.5f);
    if (i < 0) i = 0;
    if (i > BATCH - 2) i = BATCH - 2;
    while (i > 0 && (long long)i * (2 * BATCH - i - 1) / 2 > (long long)p) i--;
    while ((long long)(i + 1) * (2 * BATCH - i - 2) / 2 <= (long long)p) i++;
    long long bse = (long long)i * (2 * BATCH - i - 1) / 2;
    int j = i + 1 + (int)((long long)p - bse);
    out[BATCH + p]          = (float)__ldg(&g_nodes[i]);
    out[BATCH + NPAIRS + p] = (float)__ldg(&g_nodes[j]);
}

// ---------------- zero row counters -----------------------------------------
__global__ void k_zero() {
    int t = blockIdx.x * blockDim.x + threadIdx.x;
    if (t < NNODES) g_rcnt[t] = 0;
}

// ---------------- keygen: key = i<<18 | j<<4 | state, val = time; row hist --
__global__ void k_keygen(const int* __restrict__ edges,
                         const float* __restrict__ times,
                         const int* __restrict__ states, int E) {
    int t4 = (blockIdx.x * blockDim.x + threadIdx.x) * 4;
    if (t4 >= E) return;
    if (t4 + 3 < E) {
        int4 iv = *(const int4*)(edges + t4);
        int4 jv = *(const int4*)(edges + E + t4);
        int4 sv = *(const int4*)(states + t4);
        uint4 tv = *(const uint4*)((const unsigned int*)times + t4);
        uint4 kv;
        kv.x = ((unsigned int)iv.x << 18) | ((unsigned int)jv.x << 4) | ((unsigned int)sv.x & 1u);
        kv.y = ((unsigned int)iv.y << 18) | ((unsigned int)jv.y << 4) | ((unsigned int)sv.y & 1u);
        kv.z = ((unsigned int)iv.z << 18) | ((unsigned int)jv.z << 4) | ((unsigned int)sv.z & 1u);
        kv.w = ((unsigned int)iv.w << 18) | ((unsigned int)jv.w << 4) | ((unsigned int)sv.w & 1u);
        *(uint4*)(g_kin + t4) = kv;
        *(uint4*)(g_vin + t4) = tv;
        atomicAdd(&g_rcnt[iv.x], 1u);
        atomicAdd(&g_rcnt[iv.y], 1u);
        atomicAdd(&g_rcnt[iv.z], 1u);
        atomicAdd(&g_rcnt[iv.w], 1u);
    } else {
        for (int t = t4; t < E; t++) {
            int i = edges[t], j = edges[E + t];
            g_kin[t] = ((unsigned int)i << 18) | ((unsigned int)j << 4) |
                       ((unsigned int)states[t] & 1u);
            g_vin[t] = __float_as_uint(times[t]);
            atomicAdd(&g_rcnt[i], 1u);
        }
    }
}

// ---------------- exclusive scan of row counts -> row offsets ---------------
__global__ void __launch_bounds__(1024) k_scanrows() {
    typedef cub::BlockScan<unsigned int, 1024> Scan;
    __shared__ typename Scan::TempStorage tmp;
    int t = threadIdx.x;
    unsigned int v[10], agg = 0;
    #pragma unroll
    for (int k = 0; k < 10; k++) {
        int idx = t * 10 + k;
        v[k] = (idx < NNODES) ? g_rcnt[idx] : 0u;
        agg += v[k];
    }
    unsigned int pre, total;
    Scan(tmp).ExclusiveSum(agg, pre, total);
    unsigned int run = pre;
    #pragma unroll
    for (int k = 0; k < 10; k++) {
        int idx = t * 10 + k;
        if (idx < NNODES) g_roff[idx] = run;
        run += v[k];
    }
    if (t == 0) g_roff[NNODES] = total;
}

// ---------------- phase 2: per-row stable sort by j + fused epilogue --------
__global__ void __launch_bounds__(256) k_rows(float* __restrict__ out, int E) {
    typedef cub::BlockRadixSort<unsigned int, 256, 3> Sorter;
    __shared__ typename Sorter::TempStorage sort_tmp;
    __shared__ unsigned int keys_sm[ROWCAP];

    int r = blockIdx.x;
    unsigned int row_start = g_roff[r];
    unsigned int cnt = g_roff[r + 1] - row_start;
    if (cnt == 0) return;
    if (cnt > ROWCAP) cnt = ROWCAP;   // statistically impossible; safety clamp
    int flag_r = g_flags[r];

    // load: augmented key = j(14) << 10 | within-row original rank (10 bits)
    unsigned int ak[3];
    #pragma unroll
    for (int k = 0; k < 3; k++) {
        unsigned int p = threadIdx.x * 3u + k;
        if (p < cnt) {
            unsigned int gk = g_kout[row_start + p];
            keys_sm[p] = gk;
            ak[k] = (((gk >> 4) & 0x3FFFu) << 10) | p;
        } else {
            ak[k] = 0xFFFFFFFFu;
        }
    }
    __syncthreads();
    Sorter(sort_tmp).Sort(ak, 0, 24);   // blocked arrangement, stable by (j, rank)

    const long long OFF_E = (long long)BATCH + 2LL * NPAIRS;
    const long long OFF_T = OFF_E + 2LL * E;
    const long long OFF_S = OFF_T + E;
    const long long OFF_M = OFF_S + E;

    #pragma unroll
    for (int k = 0; k < 3; k++) {
        unsigned int p = threadIdx.x * 3u + k;   // sorted position within row
        if (p >= cnt) continue;
        unsigned int a = ak[k];
        int j = (int)(a >> 10);
        unsigned int q = a & 0x3FFu;             // original rank in row
        unsigned int gk = keys_sm[q];
        int st = (int)(gk & 1u);
        float tm = __uint_as_float(__ldg(&g_vout[row_start + q]));
        int m = flag_r & g_flags[j];
        long long t = (long long)(row_start + p);
        out[OFF_E + t]     = (float)r;
        out[OFF_E + E + t] = (float)j;
        out[OFF_T + t]     = m ? tm : 0.0f;
        out[OFF_S + t]     = m ? (float)st : 0.0f;
        out[OFF_M + t]     = (float)m;
    }
}

// ---------------- launcher ---------------------------------------------------
extern "C" void kernel_launch(void* const* d_in, const int* in_sizes, int n_in,
                              void* d_out, int out_size) {
    const int*   edges  = (const int*)d_in[0];
    const float* times  = (const float*)d_in[1];
    const int*   states = (const int*)d_in[2];
    int E = in_sizes[1];
    if (E > EMAX) E = EMAX;
    float* out = (float*)d_out;

    static cudaStream_t s_side = nullptr;
    static cudaEvent_t ev_fork = nullptr, ev_join = nullptr;
    if (s_side == nullptr) {
        cudaStreamCreateWithFlags(&s_side, cudaStreamNonBlocking);
        cudaEventCreateWithFlags(&ev_fork, cudaEventDisableTiming);
        cudaEventCreateWithFlags(&ev_join, cudaEventDisableTiming);
    }

    void *kin, *kout, *vin, *vout, *temp;
    cudaGetSymbolAddress(&kin,  g_kin);
    cudaGetSymbolAddress(&kout, g_kout);
    cudaGetSymbolAddress(&vin,  g_vin);
    cudaGetSymbolAddress(&vout, g_vout);
    cudaGetSymbolAddress(&temp, g_temp);
    const size_t temp_cap = 96u * 1024u * 1024u;

    // fork: node chain on the (single, proven) side stream
    cudaEventRecord(ev_fork, 0);
    cudaStreamWaitEvent(s_side, ev_fork, 0);
    k_scores<<<(NNODES + 255) / 256, 256, 0, s_side>>>();
    k_select<<<1, SEL_THREADS, 0, s_side>>>(out);
    k_pairs<<<(NPAIRS + 255) / 256, 256, 0, s_side>>>(out);
    cudaEventRecord(ev_join, s_side);

    // main: row histogram + keygen
    k_zero<<<(NNODES + 255) / 256, 256>>>();
    k_keygen<<<(E / 4 + 255) / 256, 256>>>(edges, times, states, E);
    k_scanrows<<<1, 1024>>>();

    // stable 2-pass radix sort on i bits [18,32)
    size_t tb = 0;
    cub::DeviceRadixSort::SortPairs(
        nullptr, tb, (const unsigned int*)kin, (unsigned int*)kout,
        (const unsigned int*)vin, (unsigned int*)vout, E, 18, 32);
    if (tb > temp_cap) tb = temp_cap;
    cub::DeviceRadixSort::SortPairs(
        temp, tb, (const unsigned int*)kin, (unsigned int*)kout,
        (const unsigned int*)vin, (unsigned int*)vout, E, 18, 32);

    // join node chain, then fused per-row sort + epilogue
    cudaStreamWaitEvent(0, ev_join, 0);
    k_rows<<<NNODES, 256>>>(out, E);
}

// round 7
// speedup vs baseline: 1.4224x; 1.4224x over previous
#include <cuda_runtime.h>
#include <cuda_bf16.h>
#include <cub/cub.cuh>
#include <math.h>

#define NNODES 10000
#define BATCH  2000
#define NPAIRS (BATCH*(BATCH-1)/2)   /* 1999000 */
#define EMAX   5000000
#define SEL_THREADS 1024
#define PB 1024                      /* hist/finish partition blocks */

// ---------------- static device scratch (no allocations allowed) -----------
__device__ unsigned int g_kin [EMAX];
__device__ unsigned int g_kout[EMAX];
__device__ unsigned int g_vin [EMAX];
__device__ unsigned int g_vout[EMAX];
__device__ unsigned int g_hist4[PB * 4];
__device__ unsigned int g_base4[4];
__device__ unsigned int g_scores[NNODES];
__device__ unsigned int g_nodes[BATCH];
__device__ int          g_flags[NNODES];
__device__ unsigned char g_temp[96u * 1024u * 1024u];

__device__ __forceinline__ unsigned int rotl32(unsigned int x, unsigned int d) {
    return (x << d) | (x >> (32u - d));
}

// ---------------- node chain: scores / select / pairs ----------------------
__global__ void k_scores() {
    int w = blockIdx.x * blockDim.x + threadIdx.x;
    if (w >= NNODES) return;
    const unsigned int k0 = 0u, k1 = 19u;
    const unsigned int ks[3] = { k0, k1, k0 ^ k1 ^ 0x1BD11BDAu };
    const unsigned int rotA[4] = {13u, 15u, 26u, 6u};
    const unsigned int rotB[4] = {17u, 29u, 16u, 24u};
    unsigned int x0 = 0u, x1 = (unsigned int)w;
    x0 += ks[0]; x1 += ks[1];
    #pragma unroll
    for (int i = 0; i < 5; i++) {
        #pragma unroll
        for (int r = 0; r < 4; r++) {
            unsigned int rot = (i & 1) ? rotB[r] : rotA[r];
            x0 += x1; x1 = rotl32(x1, rot); x1 ^= x0;
        }
        x0 += ks[(i + 1) % 3];
        x1 += ks[(i + 2) % 3] + (unsigned int)(i + 1);
    }
    unsigned int bits = x0 ^ x1;
    float f = __uint_as_float((bits >> 9) | 0x3F800000u) - 1.0f;
    float u = fmaxf(f, 1.17549435e-38f);
    float g = -logf(-logf(u));
    float s = (w > 0) ? (logf((float)w) + g) : -INFINITY;
    unsigned int b = __float_as_uint(s);
    unsigned int m = (b & 0x80000000u) ? ~b : (b | 0x80000000u);
    g_scores[w] = m;
}

__global__ void __launch_bounds__(SEL_THREADS) k_select(float* __restrict__ out) {
    __shared__ unsigned int s[NNODES];
    __shared__ unsigned int hist[256];
    __shared__ unsigned int sh_b, sh_rem, sh_run_eq, sh_run_sel;
    typedef cub::BlockScan<unsigned int, SEL_THREADS> Scan;
    __shared__ typename Scan::TempStorage scan_tmp;

    int tid = threadIdx.x;
    for (int e = tid; e < NNODES; e += SEL_THREADS) s[e] = g_scores[e];
    if (tid == 0) { sh_rem = BATCH; sh_run_eq = 0; sh_run_sel = 0; }
    __syncthreads();

    unsigned int prefix = 0;
    #pragma unroll
    for (int shift = 24; shift >= 0; shift -= 8) {
        if (tid < 256) hist[tid] = 0;
        __syncthreads();
        unsigned int mask_hi = (shift == 24) ? 0u : (0xFFFFFFFFu << (shift + 8));
        for (int e = tid; e < NNODES; e += SEL_THREADS) {
            unsigned int v = s[e];
            if (((v ^ prefix) & mask_hi) == 0u)
                atomicAdd(&hist[(v >> shift) & 255u], 1u);
        }
        __syncthreads();
        if (tid == 0) {
            unsigned int rem = sh_rem, acc = 0; int b = 0;
            for (int k = 255; k >= 0; k--) {
                unsigned int c = hist[k];
                if (acc + c >= rem) { b = k; break; }
                acc += c;
            }
            sh_b = (unsigned int)b; sh_rem = rem - acc;
        }
        __syncthreads();
        prefix |= sh_b << shift;
        __syncthreads();
    }
    unsigned int thr = prefix, rem = sh_rem;

    for (int base = 0; base < NNODES; base += SEL_THREADS) {
        int e = base + tid;
        unsigned int v = (e < NNODES) ? s[e] : 0u;
        unsigned int is_eq = (e < NNODES && v == thr) ? 1u : 0u;
        unsigned int is_gt = (e < NNODES && v >  thr) ? 1u : 0u;
        unsigned int eq_rank, eq_tot;
        Scan(scan_tmp).ExclusiveSum(is_eq, eq_rank, eq_tot);
        __syncthreads();
        unsigned int sel = is_gt | ((is_eq && (sh_run_eq + eq_rank) < rem) ? 1u : 0u);
        unsigned int pos, sel_tot;
        Scan(scan_tmp).ExclusiveSum(sel, pos, sel_tot);
        __syncthreads();
        unsigned int gpos = sh_run_sel + pos;
        if (e < NNODES) {
            g_flags[e] = (int)sel;
            if (sel) { g_nodes[gpos] = (unsigned int)e; out[gpos] = (float)e; }
        }
        __syncthreads();
        if (tid == 0) { sh_run_eq += eq_tot; sh_run_sel += sel_tot; }
        __syncthreads();
    }
}

__global__ void k_pairs(float* __restrict__ out) {
    int p = blockIdx.x * blockDim.x + threadIdx.x;
    if (p >= NPAIRS) return;
    const float A = 2.0f * BATCH - 1.0f;
    float disc = A * A - 8.0f * (float)p;
    int i = (int)((A - sqrtf(fmaxf(disc, 0.0f))) * 0.5f);
    if (i < 0) i = 0;
    if (i > BATCH - 2) i = BATCH - 2;
    while (i > 0 && (long long)i * (2 * BATCH - i - 1) / 2 > (long long)p) i--;
    while ((long long)(i + 1) * (2 * BATCH - i - 2) / 2 <= (long long)p) i++;
    long long bse = (long long)i * (2 * BATCH - i - 1) / 2;
    int j = i + 1 + (int)((long long)p - bse);
    out[BATCH + p]          = (float)__ldg(&g_nodes[i]);
    out[BATCH + NPAIRS + p] = (float)__ldg(&g_nodes[j]);
}

// ---------------- keygen: key = flat<<6 | state, val = time -----------------
__global__ void k_ekeys4(const int* __restrict__ edges,
                         const float* __restrict__ times,
                         const int* __restrict__ states, int E) {
    int t4 = (blockIdx.x * blockDim.x + threadIdx.x) * 4;
    if (t4 >= E) return;
    if (t4 + 3 < E) {
        int4 iv = *(const int4*)(edges + t4);
        int4 jv = *(const int4*)(edges + E + t4);
        int4 sv = *(const int4*)(states + t4);
        uint4 tv = *(const uint4*)((const unsigned int*)times + t4);
        uint4 kv;
        kv.x = ((unsigned int)(iv.x * NNODES - (iv.x * (iv.x + 1)) / 2 + (jv.x - iv.x - 1)) << 6) | ((unsigned int)sv.x & 1u);
        kv.y = ((unsigned int)(iv.y * NNODES - (iv.y * (iv.y + 1)) / 2 + (jv.y - iv.y - 1)) << 6) | ((unsigned int)sv.y & 1u);
        kv.z = ((unsigned int)(iv.z * NNODES - (iv.z * (iv.z + 1)) / 2 + (jv.z - iv.z - 1)) << 6) | ((unsigned int)sv.z & 1u);
        kv.w = ((unsigned int)(iv.w * NNODES - (iv.w * (iv.w + 1)) / 2 + (jv.w - iv.w - 1)) << 6) | ((unsigned int)sv.w & 1u);
        *(uint4*)(g_kin + t4) = kv;
        *(uint4*)(g_vin + t4) = tv;
    } else {
        for (int t = t4; t < E; t++) {
            int i = edges[t], j = edges[E + t];
            unsigned int flat = (unsigned int)(i * NNODES - (i * (i + 1)) / 2 + (j - i - 1));
            g_kin[t] = (flat << 6) | ((unsigned int)states[t] & 1u);
            g_vin[t] = __float_as_uint(times[t]);
        }
    }
}

// ---------------- hist pass: per-block 4-bin counts on sorted keys ----------
__global__ void __launch_bounds__(256) k_hist4(const unsigned int* __restrict__ keys,
                                               int E, int chunk) {
    __shared__ unsigned int h[4];
    int b = blockIdx.x;
    int start = b * chunk, end = min(E, start + chunk);
    if (threadIdx.x < 4) h[threadIdx.x] = 0;
    __syncthreads();
    for (int t = start + threadIdx.x; t < end; t += blockDim.x)
        atomicAdd(&h[keys[t] >> 30], 1u);
    __syncthreads();
    if (threadIdx.x < 4) g_hist4[b * 4 + threadIdx.x] = h[threadIdx.x];
}

// ---------------- scan: per-block bases + bin bases -------------------------
__global__ void __launch_bounds__(PB) k_scan4() {
    typedef cub::BlockScan<unsigned int, PB> Scan;
    __shared__ typename Scan::TempStorage tmp;
    __shared__ unsigned int tot[4];
    int t = threadIdx.x;
    unsigned int v[4];
    #pragma unroll
    for (int c = 0; c < 4; c++) v[c] = g_hist4[t * 4 + c];
    #pragma unroll
    for (int c = 0; c < 4; c++) {
        unsigned int pre, agg;
        Scan(tmp).ExclusiveSum(v[c], pre, agg);
        g_hist4[t * 4 + c] = pre;
        if (t == 0) tot[c] = agg;
        __syncthreads();
    }
    if (t == 0) {
        unsigned int off = 0;
        #pragma unroll
        for (int c = 0; c < 4; c++) { g_base4[c] = off; off += tot[c]; }
    }
}

// ---------------- finish: stable 4-bin partition fused with epilogue --------
__device__ __forceinline__ long long rowbase(int i) {
    return (long long)i * (2 * NNODES - 1 - i) / 2;
}
__device__ __forceinline__ void decode_flat(unsigned int flat, int& i, int& j) {
    const float A = 2.0f * NNODES - 1.0f;
    float disc = A * A - 8.0f * (float)flat;
    i = (int)((A - sqrtf(fmaxf(disc, 0.0f))) * 0.5f);
    if (i < 0) i = 0;
    if (i > NNODES - 2) i = NNODES - 2;
    while (i > 0 && rowbase(i) > (long long)flat) i--;
    while (rowbase(i + 1) <= (long long)flat) i++;
    j = (int)((long long)flat - rowbase(i)) + i + 1;
}

__global__ void __launch_bounds__(256) k_finish(const unsigned int* __restrict__ keys,
                                                const unsigned int* __restrict__ vals,
                                                float* __restrict__ out, int E, int chunk) {
    __shared__ unsigned int run[4];
    __shared__ unsigned int wcnt[8][4];
    __shared__ unsigned int ttot[4];
    int b = blockIdx.x;
    int start = b * chunk, end = min(E, start + chunk);
    if (threadIdx.x < 4)
        run[threadIdx.x] = g_hist4[b * 4 + threadIdx.x] + g_base4[threadIdx.x];
    __syncthreads();

    const long long OFF_E = (long long)BATCH + 2LL * NPAIRS;
    const long long OFF_T = OFF_E + 2LL * E;
    const long long OFF_S = OFF_T + E;
    const long long OFF_M = OFF_S + E;

    int warp = threadIdx.x >> 5, lane = threadIdx.x & 31;
    for (int base = start; base < end; base += blockDim.x) {
        int t = base + threadIdx.x;
        unsigned int key = 0, val = 0;
        int c = -1;
        if (t < end) { key = keys[t]; val = vals[t]; c = (int)(key >> 30); }
        unsigned int rank = 0;
        #pragma unroll
        for (int cc = 0; cc < 4; cc++) {
            unsigned int m = __ballot_sync(0xFFFFFFFFu, c == cc);
            if (c == cc) rank = __popc(m & ((1u << lane) - 1u));
            if (lane == 0) wcnt[warp][cc] = __popc(m);
        }
        __syncthreads();
        if (threadIdx.x < 4) {
            unsigned int acc = 0;
            #pragma unroll
            for (int w = 0; w < 8; w++) {
                unsigned int v = wcnt[w][threadIdx.x];
                wcnt[w][threadIdx.x] = acc;
                acc += v;
            }
            ttot[threadIdx.x] = acc;
        }
        __syncthreads();
        if (t < end) {
            unsigned int pos = run[c] + wcnt[warp][c] + rank;   // final sorted slot
            unsigned int flat = key >> 6;
            int st = (int)(key & 1u);
            int i, j; decode_flat(flat, i, j);
            int m = g_flags[i] & g_flags[j];
            out[OFF_E + pos]     = (float)i;
            out[OFF_E + E + pos] = (float)j;
            out[OFF_T + pos]     = m ? __uint_as_float(val) : 0.0f;
            out[OFF_S + pos]     = m ? (float)st : 0.0f;
            out[OFF_M + pos]     = (float)m;
        }
        __syncthreads();
        if (threadIdx.x < 4) run[threadIdx.x] += ttot[threadIdx.x];
        __syncthreads();
    }
}

// ---------------- launcher ---------------------------------------------------
extern "C" void kernel_launch(void* const* d_in, const int* in_sizes, int n_in,
                              void* d_out, int out_size) {
    const int*   edges  = (const int*)d_in[0];
    const float* times  = (const float*)d_in[1];
    const int*   states = (const int*)d_in[2];
    int E = in_sizes[1];
    if (E > EMAX) E = EMAX;
    float* out = (float*)d_out;

    static cudaStream_t s_side = nullptr;
    static cudaEvent_t ev_fork = nullptr, ev_join = nullptr;
    if (s_side == nullptr) {
        cudaStreamCreateWithFlags(&s_side, cudaStreamNonBlocking);
        cudaEventCreateWithFlags(&ev_fork, cudaEventDisableTiming);
        cudaEventCreateWithFlags(&ev_join, cudaEventDisableTiming);
    }

    void *kin, *kout, *vin, *vout, *temp;
    cudaGetSymbolAddress(&kin,  g_kin);
    cudaGetSymbolAddress(&kout, g_kout);
    cudaGetSymbolAddress(&vin,  g_vin);
    cudaGetSymbolAddress(&vout, g_vout);
    cudaGetSymbolAddress(&temp, g_temp);
    const size_t temp_cap = 96u * 1024u * 1024u;

    // fork: node chain on the single proven side stream
    cudaEventRecord(ev_fork, 0);
    cudaStreamWaitEvent(s_side, ev_fork, 0);
    k_scores<<<(NNODES + 255) / 256, 256, 0, s_side>>>();
    k_select<<<1, SEL_THREADS, 0, s_side>>>(out);
    k_pairs<<<(NPAIRS + 255) / 256, 256, 0, s_side>>>(out);
    cudaEventRecord(ev_join, s_side);

    // main: keygen
    k_ekeys4<<<(E / 4 + 255) / 256, 256>>>(edges, times, states, E);

    // 3-pass stable radix sort on bits [6,30) with explicit double buffer
    cub::DoubleBuffer<unsigned int> dk((unsigned int*)kin, (unsigned int*)kout);
    cub::DoubleBuffer<unsigned int> dv((unsigned int*)vin, (unsigned int*)vout);
    size_t tb = 0;
    cub::DeviceRadixSort::SortPairs(nullptr, tb, dk, dv, E, 6, 30);
    if (tb > temp_cap) tb = temp_cap;
    cub::DeviceRadixSort::SortPairs(temp, tb, dk, dv, E, 6, 30);
    const unsigned int* skeys = dk.Current();
    const unsigned int* svals = dv.Current();

    // stable 4-bin partition on bits [30,32) fused with epilogue
    int chunk = (E + PB - 1) / PB;
    k_hist4<<<PB, 256>>>(skeys, E, chunk);
    k_scan4<<<1, PB>>>();
    cudaStreamWaitEvent(0, ev_join, 0);
    k_finish<<<PB, 256>>>(skeys, svals, out, E, chunk);
}